// round 14
// baseline (speedup 1.0000x reference)
#include <cuda_runtime.h>
#include <math.h>

// Scalar accumulator in device global memory (no allocation allowed).
__device__ double g_sum;

__global__ void mb_init_kernel() {
    g_sum = 0.0;
}

// One warp per pair. Lane j (j<25) owns dimension j.
__global__ void __launch_bounds__(256) mb_nf1_kernel(
    const float* __restrict__ emb,   // [num_classes, 50]
    const int*   __restrict__ nf1,   // [npairs, 2]
    int npairs)
{
    const int lane    = threadIdx.x & 31;
    const int gwarp   = (blockIdx.x * blockDim.x + threadIdx.x) >> 5;
    const int nwarps  = (gridDim.x * blockDim.x) >> 5;

    float acc = 0.0f;

    for (int p = gwarp; p < npairs; p += nwarps) {
        // Uniform index load (broadcast within warp).
        const int ci = __ldg(&nf1[2 * p]);
        const int di = __ldg(&nf1[2 * p + 1]);
        const float* ec = emb + (size_t)ci * 50;
        const float* ed = emb + (size_t)di * 50;

        float t = 1.0f;   // relu(hi - lo) for this dim (identity for lanes >= 25)
        float a = 1.0f;   // 2 * |co| for this dim   (identity for lanes >= 25)
        if (lane < 25) {
            float cc = __ldg(ec + lane);
            float co = fabsf(__ldg(ec + 25 + lane));
            float dc = __ldg(ed + lane);
            float dq = fabsf(__ldg(ed + 25 + lane));
            float lo = fmaxf(cc - co, dc - dq);
            float hi = fminf(cc + co, dc + dq);
            t = fmaxf(hi - lo, 0.0f);
            a = 2.0f * co;
        }

        // Warp-wide product reduction (butterfly): all lanes end with the full product.
        #pragma unroll
        for (int off = 16; off > 0; off >>= 1) {
            t *= __shfl_xor_sync(0xffffffffu, t, off);
            a *= __shfl_xor_sync(0xffffffffu, a, off);
        }

        float loss;
        if (a == 0.0f)        loss = 0.0f;
        else if (isinf(a))    loss = 1.0f - t * (1.0f / 20000.0f);
        else                  loss = 1.0f - t / a;

        float r = fmaxf(loss, 0.0f);
        acc += r * r;   // identical on every lane; lane 0's copy is used below
    }

    // Block reduction: one partial per warp, then warp 0 reduces, one atomic per block.
    __shared__ float wsum[8];
    const int wid = threadIdx.x >> 5;
    if (lane == 0) wsum[wid] = acc;
    __syncthreads();
    if (wid == 0) {
        float v = (lane < (int)(blockDim.x >> 5)) ? wsum[lane] : 0.0f;
        #pragma unroll
        for (int off = 16; off > 0; off >>= 1)
            v += __shfl_xor_sync(0xffffffffu, v, off);
        if (lane == 0)
            atomicAdd(&g_sum, (double)v);
    }
}

__global__ void mb_finish_kernel(float* out) {
    out[0] = (float)sqrt(g_sum);
}

extern "C" void kernel_launch(void* const* d_in, const int* in_sizes, int n_in,
                              void* d_out, int out_size)
{
    const float* emb = (const float*)d_in[0];   // class_embeds: [100000, 50] fp32
    const int*   nf1 = (const int*)d_in[1];     // nf1_data:     [2000000, 2] int32
    const int npairs = in_sizes[1] / 2;

    float* out = (float*)d_out;

    mb_init_kernel<<<1, 1>>>();

    // One full wave: 148 SMs * 2048 threads = 1184 blocks of 256 (grid-stride inside).
    const int threads = 256;
    const int blocks  = 1184;
    mb_nf1_kernel<<<blocks, threads>>>(emb, nf1, npairs);

    mb_finish_kernel<<<1, 1>>>(out);
}

// round 15
// speedup vs baseline: 1.0006x; 1.0006x over previous
#include <cuda_runtime.h>
#include <math.h>

// Scalar accumulator in device global memory (no allocation allowed).
__device__ double g_sum;

__global__ void mb_init_kernel() {
    g_sum = 0.0;
}

// One warp per pair. Lane j (j<25) owns dimension j.
__global__ void __launch_bounds__(256) mb_nf1_kernel(
    const float* __restrict__ emb,   // [num_classes, 50]
    const int*   __restrict__ nf1,   // [npairs, 2]
    int npairs)
{
    const int lane    = threadIdx.x & 31;
    const int gwarp   = (blockIdx.x * blockDim.x + threadIdx.x) >> 5;
    const int nwarps  = (gridDim.x * blockDim.x) >> 5;

    float acc = 0.0f;

    for (int p = gwarp; p < npairs; p += nwarps) {
        // Uniform index load (broadcast within warp).
        const int ci = __ldg(&nf1[2 * p]);
        const int di = __ldg(&nf1[2 * p + 1]);
        const float* ec = emb + (size_t)ci * 50;
        const float* ed = emb + (size_t)di * 50;

        float t = 1.0f;   // relu(hi - lo) for this dim (identity for lanes >= 25)
        float a = 1.0f;   // 2 * |co| for this dim   (identity for lanes >= 25)
        if (lane < 25) {
            float cc = __ldg(ec + lane);
            float co = fabsf(__ldg(ec + 25 + lane));
            float dc = __ldg(ed + lane);
            float dq = fabsf(__ldg(ed + 25 + lane));
            float lo = fmaxf(cc - co, dc - dq);
            float hi = fminf(cc + co, dc + dq);
            t = fmaxf(hi - lo, 0.0f);
            a = 2.0f * co;
        }

        // Warp-wide product reduction (butterfly): all lanes end with the full product.
        #pragma unroll
        for (int off = 16; off > 0; off >>= 1) {
            t *= __shfl_xor_sync(0xffffffffu, t, off);
            a *= __shfl_xor_sync(0xffffffffu, a, off);
        }

        float loss;
        if (a == 0.0f)        loss = 0.0f;
        else if (isinf(a))    loss = 1.0f - t * (1.0f / 20000.0f);
        else                  loss = 1.0f - t / a;

        float r = fmaxf(loss, 0.0f);
        acc += r * r;   // identical on every lane; lane 0's copy is used below
    }

    // Block reduction: one partial per warp, then warp 0 reduces, one atomic per block.
    __shared__ float wsum[8];
    const int wid = threadIdx.x >> 5;
    if (lane == 0) wsum[wid] = acc;
    __syncthreads();
    if (wid == 0) {
        float v = (lane < (int)(blockDim.x >> 5)) ? wsum[lane] : 0.0f;
        #pragma unroll
        for (int off = 16; off > 0; off >>= 1)
            v += __shfl_xor_sync(0xffffffffu, v, off);
        if (lane == 0)
            atomicAdd(&g_sum, (double)v);
    }
}

__global__ void mb_finish_kernel(float* out) {
    out[0] = (float)sqrt(g_sum);
}

extern "C" void kernel_launch(void* const* d_in, const int* in_sizes, int n_in,
                              void* d_out, int out_size)
{
    const float* emb = (const float*)d_in[0];   // class_embeds: [100000, 50] fp32
    const int*   nf1 = (const int*)d_in[1];     // nf1_data:     [2000000, 2] int32
    const int npairs = in_sizes[1] / 2;

    float* out = (float*)d_out;

    mb_init_kernel<<<1, 1>>>();

    // One full wave: 148 SMs * 2048 threads = 1184 blocks of 256 (grid-stride inside).
    const int threads = 256;
    const int blocks  = 1184;
    mb_nf1_kernel<<<blocks, threads>>>(emb, nf1, npairs);

    mb_finish_kernel<<<1, 1>>>(out);
}

// round 16
// speedup vs baseline: 1.0015x; 1.0009x over previous
#include <cuda_runtime.h>
#include <math.h>

// Scalar accumulator in device global memory (no allocation allowed).
__device__ double g_sum;

__global__ void mb_init_kernel() {
    g_sum = 0.0;
}

// One warp per pair. Lane j (j<25) owns dimension j.
__global__ void __launch_bounds__(256) mb_nf1_kernel(
    const float* __restrict__ emb,   // [num_classes, 50]
    const int*   __restrict__ nf1,   // [npairs, 2]
    int npairs)
{
    const int lane    = threadIdx.x & 31;
    const int gwarp   = (blockIdx.x * blockDim.x + threadIdx.x) >> 5;
    const int nwarps  = (gridDim.x * blockDim.x) >> 5;

    float acc = 0.0f;

    for (int p = gwarp; p < npairs; p += nwarps) {
        // Uniform index load (broadcast within warp).
        const int ci = __ldg(&nf1[2 * p]);
        const int di = __ldg(&nf1[2 * p + 1]);
        const float* ec = emb + (size_t)ci * 50;
        const float* ed = emb + (size_t)di * 50;

        float t = 1.0f;   // relu(hi - lo) for this dim (identity for lanes >= 25)
        float a = 1.0f;   // 2 * |co| for this dim   (identity for lanes >= 25)
        if (lane < 25) {
            float cc = __ldg(ec + lane);
            float co = fabsf(__ldg(ec + 25 + lane));
            float dc = __ldg(ed + lane);
            float dq = fabsf(__ldg(ed + 25 + lane));
            float lo = fmaxf(cc - co, dc - dq);
            float hi = fminf(cc + co, dc + dq);
            t = fmaxf(hi - lo, 0.0f);
            a = 2.0f * co;
        }

        // Warp-wide product reduction (butterfly): all lanes end with the full product.
        #pragma unroll
        for (int off = 16; off > 0; off >>= 1) {
            t *= __shfl_xor_sync(0xffffffffu, t, off);
            a *= __shfl_xor_sync(0xffffffffu, a, off);
        }

        float loss;
        if (a == 0.0f)        loss = 0.0f;
        else if (isinf(a))    loss = 1.0f - t * (1.0f / 20000.0f);
        else                  loss = 1.0f - t / a;

        float r = fmaxf(loss, 0.0f);
        acc += r * r;   // identical on every lane; lane 0's copy is used below
    }

    // Block reduction: one partial per warp, then warp 0 reduces, one atomic per block.
    __shared__ float wsum[8];
    const int wid = threadIdx.x >> 5;
    if (lane == 0) wsum[wid] = acc;
    __syncthreads();
    if (wid == 0) {
        float v = (lane < (int)(blockDim.x >> 5)) ? wsum[lane] : 0.0f;
        #pragma unroll
        for (int off = 16; off > 0; off >>= 1)
            v += __shfl_xor_sync(0xffffffffu, v, off);
        if (lane == 0)
            atomicAdd(&g_sum, (double)v);
    }
}

__global__ void mb_finish_kernel(float* out) {
    out[0] = (float)sqrt(g_sum);
}

extern "C" void kernel_launch(void* const* d_in, const int* in_sizes, int n_in,
                              void* d_out, int out_size)
{
    const float* emb = (const float*)d_in[0];   // class_embeds: [100000, 50] fp32
    const int*   nf1 = (const int*)d_in[1];     // nf1_data:     [2000000, 2] int32
    const int npairs = in_sizes[1] / 2;

    float* out = (float*)d_out;

    mb_init_kernel<<<1, 1>>>();

    // One full wave: 148 SMs * 2048 threads = 1184 blocks of 256 (grid-stride inside).
    const int threads = 256;
    const int blocks  = 1184;
    mb_nf1_kernel<<<blocks, threads>>>(emb, nf1, npairs);

    mb_finish_kernel<<<1, 1>>>(out);
}

// round 17
// speedup vs baseline: 1.0076x; 1.0061x over previous
#include <cuda_runtime.h>
#include <math.h>

// Scalar accumulator in device global memory (no allocation allowed).
__device__ double g_sum;

__global__ void mb_init_kernel() {
    g_sum = 0.0;
}

// One warp per pair. Lane j (j<25) owns dimension j.
__global__ void __launch_bounds__(256) mb_nf1_kernel(
    const float* __restrict__ emb,   // [num_classes, 50]
    const int*   __restrict__ nf1,   // [npairs, 2]
    int npairs)
{
    const int lane    = threadIdx.x & 31;
    const int gwarp   = (blockIdx.x * blockDim.x + threadIdx.x) >> 5;
    const int nwarps  = (gridDim.x * blockDim.x) >> 5;

    float acc = 0.0f;

    for (int p = gwarp; p < npairs; p += nwarps) {
        // Uniform index load (broadcast within warp).
        const int ci = __ldg(&nf1[2 * p]);
        const int di = __ldg(&nf1[2 * p + 1]);
        const float* ec = emb + (size_t)ci * 50;
        const float* ed = emb + (size_t)di * 50;

        float t = 1.0f;   // relu(hi - lo) for this dim (identity for lanes >= 25)
        float a = 1.0f;   // 2 * |co| for this dim   (identity for lanes >= 25)
        if (lane < 25) {
            float cc = __ldg(ec + lane);
            float co = fabsf(__ldg(ec + 25 + lane));
            float dc = __ldg(ed + lane);
            float dq = fabsf(__ldg(ed + 25 + lane));
            float lo = fmaxf(cc - co, dc - dq);
            float hi = fminf(cc + co, dc + dq);
            t = fmaxf(hi - lo, 0.0f);
            a = 2.0f * co;
        }

        // Warp-wide product reduction (butterfly): all lanes end with the full product.
        #pragma unroll
        for (int off = 16; off > 0; off >>= 1) {
            t *= __shfl_xor_sync(0xffffffffu, t, off);
            a *= __shfl_xor_sync(0xffffffffu, a, off);
        }

        float loss;
        if (a == 0.0f)        loss = 0.0f;
        else if (isinf(a))    loss = 1.0f - t * (1.0f / 20000.0f);
        else                  loss = 1.0f - t / a;

        float r = fmaxf(loss, 0.0f);
        acc += r * r;   // identical on every lane; lane 0's copy is used below
    }

    // Block reduction: one partial per warp, then warp 0 reduces, one atomic per block.
    __shared__ float wsum[8];
    const int wid = threadIdx.x >> 5;
    if (lane == 0) wsum[wid] = acc;
    __syncthreads();
    if (wid == 0) {
        float v = (lane < (int)(blockDim.x >> 5)) ? wsum[lane] : 0.0f;
        #pragma unroll
        for (int off = 16; off > 0; off >>= 1)
            v += __shfl_xor_sync(0xffffffffu, v, off);
        if (lane == 0)
            atomicAdd(&g_sum, (double)v);
    }
}

__global__ void mb_finish_kernel(float* out) {
    out[0] = (float)sqrt(g_sum);
}

extern "C" void kernel_launch(void* const* d_in, const int* in_sizes, int n_in,
                              void* d_out, int out_size)
{
    const float* emb = (const float*)d_in[0];   // class_embeds: [100000, 50] fp32
    const int*   nf1 = (const int*)d_in[1];     // nf1_data:     [2000000, 2] int32
    const int npairs = in_sizes[1] / 2;

    float* out = (float*)d_out;

    mb_init_kernel<<<1, 1>>>();

    // One full wave: 148 SMs * 2048 threads = 1184 blocks of 256 (grid-stride inside).
    const int threads = 256;
    const int blocks  = 1184;
    mb_nf1_kernel<<<blocks, threads>>>(emb, nf1, npairs);

    mb_finish_kernel<<<1, 1>>>(out);
}